// round 15
// baseline (speedup 1.0000x reference)
#include <cuda_runtime.h>

#define KNN_K 16
#define NBZ   96
#define NBY   256
#define NBB   (NBZ * NBY)
#define C0    64       // bootstrap candidate-count target
#define MAXN  8
#define MAXP  8192
#define FULLM 0xffffffffu
#define FINF  __int_as_float(0x7f800000)

// Fixed bin bounds: correctness holds for ANY bounds (clamped partition);
// these only tune bin quality for ~N(0,1) data.
#define BMIN  (-6.0f)
#define BRNG  (12.0f)
#define WZ    (BRNG / NBZ)
#define INVZ  (NBZ / BRNG)
#define INVY  (NBY / BRNG)

// Static scratch (allocations are forbidden).
__device__ float4 g_pack[MAXN * MAXP];      // bin-sorted targets (x,y,z,idx-bits)
__device__ float  g_s2[MAXN * MAXP];        // bin-sorted ||p2||^2 (reference rounding)
__device__ int    g_qidx[MAXN * MAXP];      // bin-sorted query original index
__device__ int    g_bstart[MAXN * (NBB + 1)];
__device__ int    g_cnt[MAXN * NBB];        // hist counts -> scatter cursors
__device__ int    g_qcnt[MAXN * NBB];

// ||p||^2 with reference rounding: rn(rn(x*x + y*y) + z*z), products rounded.
__device__ __forceinline__ float sumsq_ref(float x, float y, float z) {
    return __fadd_rn(__fadd_rn(__fmul_rn(x, x), __fmul_rn(y, y)),
                     __fmul_rn(z, z));
}

__device__ __forceinline__ int binz(float z) {
    int b = (int)((z - BMIN) * INVZ);
    return min(NBZ - 1, max(0, b));
}
__device__ __forceinline__ int biny(float y) {
    int b = (int)((y - BMIN) * INVY);
    return min(NBY - 1, max(0, b));
}

__global__ void zero_hist_kernel(int Nn) {
    int t = blockIdx.x * blockDim.x + threadIdx.x;
    if (t < Nn * NBB) { g_cnt[t] = 0; g_qcnt[t] = 0; }
}

__global__ void hist_kernel(const float* __restrict__ p1,
                            const float* __restrict__ p2,
                            const int* __restrict__ len1,
                            const int* __restrict__ len2,
                            int Nn, int P1, int P2) {
    int t = blockIdx.x * blockDim.x + threadIdx.x;
    int P = max(P1, P2);
    if (t >= Nn * P) return;
    int n = t / P;
    int j = t - n * P;
    if (j < P2 && j < __ldg(&len2[n])) {
        const float* p = p2 + ((size_t)n * P2 + j) * 3;
        atomicAdd(&g_cnt[n * NBB + binz(p[2]) * NBY + biny(p[1])], 1);
    }
    if (j < P1 && j < __ldg(&len1[n])) {
        const float* p = p1 + ((size_t)n * P1 + j) * 3;
        atomicAdd(&g_qcnt[n * NBB + binz(p[2]) * NBY + biny(p[1])], 1);
    }
}

// One block per batch (1024 threads): two-level warp-scan exclusive scan.
__global__ __launch_bounds__(1024) void scan_kernel(int Nn) {
    int n = blockIdx.x, tid = threadIdx.x;
    int lane = tid & 31, wid = tid >> 5;
    __shared__ int part[1024];
    __shared__ int wsum[32];
    const int BPT = NBB / 1024;              // 24 bins per thread

#define DO_SCAN(SRC, WRITE_BSTART)                                             \
    {                                                                          \
        int base = tid * BPT;                                                  \
        int cnts[BPT];                                                         \
        int s = 0;                                                             \
        _Pragma("unroll")                                                      \
        for (int k = 0; k < BPT; k++) {                                        \
            cnts[k] = SRC[n * NBB + base + k]; s += cnts[k];                   \
        }                                                                      \
        part[tid] = s; __syncthreads();                                        \
        int v = part[tid];                                                     \
        int inc = v;                                                           \
        _Pragma("unroll")                                                      \
        for (int o = 1; o < 32; o <<= 1) {                                     \
            int u = __shfl_up_sync(FULLM, inc, o);                             \
            if (lane >= o) inc += u;                                           \
        }                                                                      \
        if (lane == 31) wsum[wid] = inc;                                       \
        __syncthreads();                                                       \
        if (wid == 0) {                                                        \
            int w = wsum[lane];                                                \
            int winc = w;                                                      \
            _Pragma("unroll")                                                  \
            for (int o = 1; o < 32; o <<= 1) {                                 \
                int u = __shfl_up_sync(FULLM, winc, o);                        \
                if (lane >= o) winc += u;                                      \
            }                                                                  \
            wsum[lane] = winc - w;                                             \
        }                                                                      \
        __syncthreads();                                                       \
        int run = inc - v + wsum[wid];                                         \
        _Pragma("unroll")                                                      \
        for (int k = 0; k < BPT; k++) {                                        \
            int b = base + k;                                                  \
            if (WRITE_BSTART) g_bstart[n * (NBB + 1) + b] = run;               \
            SRC[n * NBB + b] = run;                                            \
            run += cnts[k];                                                    \
        }                                                                      \
        if (WRITE_BSTART && tid == 1023)                                       \
            g_bstart[n * (NBB + 1) + NBB] = run;                               \
        __syncthreads();                                                       \
    }

    DO_SCAN(g_cnt, 1)
    DO_SCAN(g_qcnt, 0)
#undef DO_SCAN
}

__global__ void scatter_kernel(const float* __restrict__ p1,
                               const float* __restrict__ p2,
                               const int* __restrict__ len1,
                               const int* __restrict__ len2,
                               int Nn, int P1, int P2) {
    int t = blockIdx.x * blockDim.x + threadIdx.x;
    int P = max(P1, P2);
    if (t >= Nn * P) return;
    int n = t / P;
    int j = t - n * P;
    if (j < P2 && j < __ldg(&len2[n])) {
        const float* p = p2 + ((size_t)n * P2 + j) * 3;
        float x = p[0], y = p[1], z = p[2];
        int b = binz(z) * NBY + biny(y);
        int pos = atomicAdd(&g_cnt[n * NBB + b], 1);
        g_pack[n * MAXP + pos] = make_float4(x, y, z, __int_as_float(j));
        g_s2[n * MAXP + pos] = sumsq_ref(x, y, z);
    }
    if (j < P1 && j < __ldg(&len1[n])) {
        const float* p = p1 + ((size_t)n * P1 + j) * 3;
        int b = binz(p[2]) * NBY + biny(p[1]);
        int pos = atomicAdd(&g_qcnt[n * NBB + b], 1);
        g_qidx[n * MAXP + pos] = j;
    }
}

#define LEX_LT(da, ia, db, ib) (((da) < (db)) || (((da) == (db)) && ((ia) < (ib))))

// Warp bitonic sort-32 (ascending lex) of (d, jj) across lanes.
#define BSORT32(d, jj)                                                         \
    _Pragma("unroll")                                                          \
    for (int k = 2; k <= 32; k <<= 1) {                                        \
        _Pragma("unroll")                                                      \
        for (int j = k >> 1; j > 0; j >>= 1) {                                 \
            float od = __shfl_xor_sync(FULLM, d, j);                           \
            int   oj = __shfl_xor_sync(FULLM, jj, j);                          \
            bool up = ((lane & k) == 0);                                       \
            bool want_min = (((lane & j) == 0) == up);                         \
            bool mine_lt = LEX_LT(d, jj, od, oj);                              \
            bool take = (mine_lt != want_min);                                 \
            d = take ? od : d;                                                 \
            jj = take ? oj : jj;                                               \
        }                                                                      \
    }

// One warp per query; warp-distributed sorted top list (lane k = k-th best,
// lex on (d, idx); lanes 16..31 sorted overflow).
__global__ __launch_bounds__(256) void knn_kernel(
    const float* __restrict__ p1,
    const int* __restrict__ len1,
    float* __restrict__ out,
    int Nn, int P1, int P2, long long NPK) {

    int gw = (blockIdx.x * blockDim.x + threadIdx.x) >> 5;
    int lane = threadIdx.x & 31;
    if (gw >= Nn * P1) return;
    int n = gw / P1;
    int qs = gw - n * P1;
    int L1 = __ldg(&len1[n]);
    if (qs >= L1) {
        // Padded slots [L1,P1) biject onto padded rows i=qs: write zeros here.
        if (lane < KNN_K) {
            long long o = ((long long)n * P1 + qs) * KNN_K;
            out[o + lane] = 0.0f;
            out[NPK + o + lane] = 0.0f;
        }
        return;
    }

    int i = __ldg(&g_qidx[n * MAXP + qs]);
    const float* p = p1 + ((size_t)n * P1 + i) * 3;
    float x1 = __ldg(&p[0]), y1 = __ldg(&p[1]), z1 = __ldg(&p[2]);
    float s1 = sumsq_ref(x1, y1, z1);

    const float4* pk = g_pack + (size_t)n * MAXP;
    const float* ps2 = g_s2 + (size_t)n * MAXP;
    const int* bs = g_bstart + n * (NBB + 1);

    int bz = binz(z1);
    int by = biny(y1);

    float ld = FINF; int lj = 0x7fffffff;
    float b15d = FINF; int b15j = 0x7fffffff;
    bool inited = false;
    const float eps = 1e-4f;

    auto scan = [&](int from, int to) {
        int base = from;
        if (!inited && from < to) {
            int t = from + lane;
            float d; int jj;
            if (t < to) {
                float4 q = __ldg(&pk[t]);
                float s2 = __ldg(&ps2[t]);
                float dot = __fmaf_rn(z1, q.z,
                            __fmaf_rn(y1, q.y,
                            __fmul_rn(x1, q.x)));
                d = __fmaf_rn(-2.0f, dot, __fadd_rn(s1, s2));
                jj = __float_as_int(q.w);
            } else { d = FINF; jj = 0x7fffffff; }
            BSORT32(d, jj)
            ld = d; lj = jj;
            b15d = __shfl_sync(FULLM, ld, 15);
            b15j = __shfl_sync(FULLM, lj, 15);
            inited = true;
            base = from + 32;
        }
        for (; base < to; base += 32) {
            int t = base + lane;
            float d; int jj;
            if (t < to) {
                float4 q = __ldg(&pk[t]);
                float s2 = __ldg(&ps2[t]);
                float dot = __fmaf_rn(z1, q.z,
                            __fmaf_rn(y1, q.y,
                            __fmul_rn(x1, q.x)));
                d = __fmaf_rn(-2.0f, dot, __fadd_rn(s1, s2));
                jj = __float_as_int(q.w);
            } else { d = FINF; jj = 0x7fffffff; }
            bool acc = LEX_LT(d, jj, b15d, b15j);
            unsigned am = __ballot_sync(FULLM, acc);
            if (!am) continue;
            if (__popc(am) >= 6) {
                // Bulk path: sort batch, bitonic-merge with list (keep lowest 32).
                BSORT32(d, jj)
                float rd = __shfl_sync(FULLM, d, 31 - lane);
                int   rj = __shfl_sync(FULLM, jj, 31 - lane);
                bool keep = LEX_LT(ld, lj, rd, rj);
                float md = keep ? ld : rd;
                int   mj = keep ? lj : rj;
#pragma unroll
                for (int j = 16; j > 0; j >>= 1) {
                    float od = __shfl_xor_sync(FULLM, md, j);
                    int   oj = __shfl_xor_sync(FULLM, mj, j);
                    bool lower = ((lane & j) == 0);
                    bool mine_lt = LEX_LT(md, mj, od, oj);
                    bool take = (mine_lt != lower);
                    md = take ? od : md;
                    mj = take ? oj : mj;
                }
                ld = md; lj = mj;
            } else {
                while (am) {
                    int src = __ffs(am) - 1;
                    am &= am - 1;
                    float cd = __shfl_sync(FULLM, d, src);
                    int   cj = __shfl_sync(FULLM, jj, src);
                    float pd = __shfl_up_sync(FULLM, ld, 1);
                    int   pj = __shfl_up_sync(FULLM, lj, 1);
                    if (LEX_LT(cd, cj, ld, lj)) {
                        bool here = (lane == 0) || LEX_LT(pd, pj, cd, cj);
                        ld = here ? cd : pd;
                        lj = here ? cj : pj;
                    }
                }
            }
            b15d = __shfl_sync(FULLM, ld, 15);
            b15j = __shfl_sync(FULLM, lj, 15);
        }
    };

    // y-window [yl, yr] for half-width h around y1 (float-clamped: h may be inf).
    auto ybounds = [&](float h, int& yl, int& yr) {
        float fl = (y1 - h - BMIN) * INVY;
        float fr = (y1 + h - BMIN) * INVY;
        yl = (int)fminf(fmaxf(fl, 0.0f), (float)(NBY - 1));
        yr = (int)fminf(fmaxf(fr, 0.0f), (float)(NBY - 1));
    };

    // Bootstrap: register-preloaded boundaries bs[rowb+by-15 .. by+16] (one
    // coalesced lane load); the count expansion runs on shfl, no memory.
    int rowb = bz * NBY;
    int pbase = by - 15;                       // boundary idx offset within row
    {
        int bidx = min(max(pbase + lane, 0), NBY);
        int pv = __ldg(&bs[rowb + bidx]);
        auto bget = [&](int yb) -> int {       // boundary at row offset yb (0..NBY)
            if (yb >= pbase && yb < pbase + 32)
                return __shfl_sync(FULLM, pv, yb - pbase);
            return __ldg(&bs[rowb + yb]);
        };

        int ylo0 = by, yhi0 = by;
        int from = bget(ylo0), to = bget(yhi0 + 1);
        bool side = true;
        while (to - from < C0) {
            bool canR = (yhi0 < NBY - 1), canL = (ylo0 > 0);
            if (!canR && !canL) break;
            if ((side && canR) || !canL) { yhi0++; to = bget(yhi0 + 1); }
            else { ylo0--; from = bget(ylo0); }
            side = !side;
        }
        scan(from, to);

        // Own-row remainder (disjoint; stale tau => superset, exact).
        float tau = b15d;
        float h = sqrtf(fmaxf(tau + eps, 0.0f));
        int yl, yr; ybounds(h, yl, yr);
        if (yl < ylo0) scan(bget(yl), bget(ylo0));
        if (yr > yhi0) scan(bget(yhi0 + 1), bget(yr + 1));
    }

    // Rows outward with exact per-direction stop.
    int up = bz + 1, dn = bz - 1;
    bool uo = true, dno = true;
    while (uo || dno) {
        if (uo) {
            if (up >= NBZ) uo = false;
            else {
                float dz = fmaxf(BMIN + (float)up * WZ - z1, 0.0f);
                float tau = b15d;
                if (dz * dz > tau + eps) uo = false;
                else {
                    float h = sqrtf(fmaxf(tau + eps - dz * dz, 0.0f));
                    int yl, yr; ybounds(h, yl, yr);
                    int rb = up * NBY;
                    scan(__ldg(&bs[rb + yl]), __ldg(&bs[rb + yr + 1]));
                    up++;
                }
            }
        }
        if (dno) {
            if (dn < 0) dno = false;
            else {
                float dz = fmaxf(z1 - (BMIN + (float)(dn + 1) * WZ), 0.0f);
                float tau = b15d;
                if (dz * dz > tau + eps) dno = false;
                else {
                    float h = sqrtf(fmaxf(tau + eps - dz * dz, 0.0f));
                    int yl, yr; ybounds(h, yl, yr);
                    int rb = dn * NBY;
                    scan(__ldg(&bs[rb + yl]), __ldg(&bs[rb + yr + 1]));
                    dn--;
                }
            }
        }
    }

    if (lane < KNN_K) {
        long long o = ((long long)n * P1 + i) * KNN_K;
        out[o + lane] = (float)lj;
        out[NPK + o + lane] = ld;
    }
}

extern "C" void kernel_launch(void* const* d_in, const int* in_sizes, int n_in,
                              void* d_out, int out_size) {
    const float* pts[2] = {0, 0};
    const int* lens[2] = {0, 0};
    int lsz[2] = {0, 0};
    int psz[2] = {0, 0};
    int npts = 0, nlen = 0;
    for (int i = 0; i < n_in; i++) {
        if (in_sizes[i] <= 1024) {
            if (nlen < 2) { lens[nlen] = (const int*)d_in[i]; lsz[nlen] = in_sizes[i]; nlen++; }
        } else {
            if (npts < 2) { pts[npts] = (const float*)d_in[i]; psz[npts] = in_sizes[i]; npts++; }
        }
    }
    const float* p1 = pts[0];
    const float* p2 = pts[1];
    const int* l1 = lens[0];
    const int* l2 = lens[1];

    int Nn = lsz[0];
    int P1 = psz[0] / (3 * Nn);
    int P2 = psz[1] / (3 * Nn);
    long long NPK = (long long)out_size / 2;   // first half idx, second half dists

    int P = (P1 > P2) ? P1 : P2;
    int ptblocks = (Nn * P + 255) / 256;

    zero_hist_kernel<<<(Nn * NBB + 255) / 256, 256>>>(Nn);
    hist_kernel<<<ptblocks, 256>>>(p1, p2, l1, l2, Nn, P1, P2);
    scan_kernel<<<Nn, 1024>>>(Nn);
    scatter_kernel<<<ptblocks, 256>>>(p1, p2, l1, l2, Nn, P1, P2);

    long long threads = (long long)Nn * P1 * 32;
    int blocks = (int)((threads + 255) / 256);
    knn_kernel<<<blocks, 256>>>(p1, l1, (float*)d_out, Nn, P1, P2, NPK);
}

// round 16
// speedup vs baseline: 1.5238x; 1.5238x over previous
#include <cuda_runtime.h>

#define KNN_K 16
#define NBZ   64
#define NBY   64
#define NBB   (NBZ * NBY)
#define H0    0.22f    // bootstrap y half-width (distance units)
#define MAXN  8
#define MAXP  8192
#define FULLM 0xffffffffu
#define FINF  __int_as_float(0x7f800000)

// Fixed bin bounds: correctness holds for ANY bounds (clamped partition);
// these only tune bin quality for ~N(0,1) data.
#define BMIN  (-6.0f)
#define BRNG  (12.0f)
#define WZ    (BRNG / NBZ)
#define INVZ  (NBZ / BRNG)
#define INVY  (NBY / BRNG)

// Static scratch (allocations are forbidden).
__device__ float4 g_pack[MAXN * MAXP];      // bin-sorted targets (x,y,z,idx-bits)
__device__ float  g_s2[MAXN * MAXP];        // bin-sorted ||p2||^2 (reference rounding)
__device__ int    g_qidx[MAXN * MAXP];      // bin-sorted query original index
__device__ int    g_bstart[MAXN * (NBB + 1)];
__device__ int    g_cnt[MAXN * NBB];        // hist counts -> scatter cursors
__device__ int    g_qcnt[MAXN * NBB];

// ||p||^2 with reference rounding: rn(rn(x*x + y*y) + z*z), products rounded.
__device__ __forceinline__ float sumsq_ref(float x, float y, float z) {
    return __fadd_rn(__fadd_rn(__fmul_rn(x, x), __fmul_rn(y, y)),
                     __fmul_rn(z, z));
}

__device__ __forceinline__ int binz(float z) {
    int b = (int)((z - BMIN) * INVZ);
    return min(NBZ - 1, max(0, b));
}
__device__ __forceinline__ int biny(float y) {
    int b = (int)((y - BMIN) * INVY);
    return min(NBY - 1, max(0, b));
}

__global__ void zero_hist_kernel(int Nn) {
    int t = blockIdx.x * blockDim.x + threadIdx.x;
    if (t < Nn * NBB) { g_cnt[t] = 0; g_qcnt[t] = 0; }
}

__global__ void hist_kernel(const float* __restrict__ p1,
                            const float* __restrict__ p2,
                            const int* __restrict__ len1,
                            const int* __restrict__ len2,
                            int Nn, int P1, int P2) {
    int t = blockIdx.x * blockDim.x + threadIdx.x;
    int P = max(P1, P2);
    if (t >= Nn * P) return;
    int n = t / P;
    int j = t - n * P;
    if (j < P2 && j < __ldg(&len2[n])) {
        const float* p = p2 + ((size_t)n * P2 + j) * 3;
        atomicAdd(&g_cnt[n * NBB + binz(p[2]) * NBY + biny(p[1])], 1);
    }
    if (j < P1 && j < __ldg(&len1[n])) {
        const float* p = p1 + ((size_t)n * P1 + j) * 3;
        atomicAdd(&g_qcnt[n * NBB + binz(p[2]) * NBY + biny(p[1])], 1);
    }
}

// One block per batch: two-level exclusive scan of both histograms.
__global__ void scan_kernel(int Nn) {
    int n = blockIdx.x, tid = threadIdx.x;   // 256 threads
    __shared__ int part[256];
    const int BPT = NBB / 256;               // 16 bins per thread

    {
        int base = tid * BPT;
        int cnts[BPT];
        int s = 0;
#pragma unroll
        for (int k = 0; k < BPT; k++) { cnts[k] = g_cnt[n * NBB + base + k]; s += cnts[k]; }
        part[tid] = s; __syncthreads();
        if (tid == 0) {
            int run = 0;
            for (int t = 0; t < 256; t++) { int v = part[t]; part[t] = run; run += v; }
        }
        __syncthreads();
        int run = part[tid];
#pragma unroll
        for (int k = 0; k < BPT; k++) {
            int b = base + k;
            g_bstart[n * (NBB + 1) + b] = run;
            g_cnt[n * NBB + b] = run;
            run += cnts[k];
        }
        if (tid == 255) g_bstart[n * (NBB + 1) + NBB] = run;
        __syncthreads();
    }
    {
        int base = tid * BPT;
        int cnts[BPT];
        int s = 0;
#pragma unroll
        for (int k = 0; k < BPT; k++) { cnts[k] = g_qcnt[n * NBB + base + k]; s += cnts[k]; }
        part[tid] = s; __syncthreads();
        if (tid == 0) {
            int run = 0;
            for (int t = 0; t < 256; t++) { int v = part[t]; part[t] = run; run += v; }
        }
        __syncthreads();
        int run = part[tid];
#pragma unroll
        for (int k = 0; k < BPT; k++) {
            g_qcnt[n * NBB + base + k] = run;
            run += cnts[k];
        }
    }
}

__global__ void scatter_kernel(const float* __restrict__ p1,
                               const float* __restrict__ p2,
                               const int* __restrict__ len1,
                               const int* __restrict__ len2,
                               int Nn, int P1, int P2) {
    int t = blockIdx.x * blockDim.x + threadIdx.x;
    int P = max(P1, P2);
    if (t >= Nn * P) return;
    int n = t / P;
    int j = t - n * P;
    if (j < P2 && j < __ldg(&len2[n])) {
        const float* p = p2 + ((size_t)n * P2 + j) * 3;
        float x = p[0], y = p[1], z = p[2];
        int b = binz(z) * NBY + biny(y);
        int pos = atomicAdd(&g_cnt[n * NBB + b], 1);
        g_pack[n * MAXP + pos] = make_float4(x, y, z, __int_as_float(j));
        g_s2[n * MAXP + pos] = sumsq_ref(x, y, z);
    }
    if (j < P1 && j < __ldg(&len1[n])) {
        const float* p = p1 + ((size_t)n * P1 + j) * 3;
        int b = binz(p[2]) * NBY + biny(p[1]);
        int pos = atomicAdd(&g_qcnt[n * NBB + b], 1);
        g_qidx[n * MAXP + pos] = j;
    }
}

#define LEX_LT(da, ia, db, ib) (((da) < (db)) || (((da) == (db)) && ((ia) < (ib))))

// Warp bitonic sort-32 (ascending lex) of (d, jj) across lanes.
#define BSORT32(d, jj)                                                         \
    _Pragma("unroll")                                                          \
    for (int k = 2; k <= 32; k <<= 1) {                                        \
        _Pragma("unroll")                                                      \
        for (int j = k >> 1; j > 0; j >>= 1) {                                 \
            float od = __shfl_xor_sync(FULLM, d, j);                           \
            int   oj = __shfl_xor_sync(FULLM, jj, j);                          \
            bool up = ((lane & k) == 0);                                       \
            bool want_min = (((lane & j) == 0) == up);                         \
            bool mine_lt = LEX_LT(d, jj, od, oj);                              \
            bool take = (mine_lt != want_min);                                 \
            d = take ? od : d;                                                 \
            jj = take ? oj : jj;                                               \
        }                                                                      \
    }

// One warp per query; warp-distributed sorted top list (lane k = k-th best,
// lex on (d, idx); lanes 16..31 sorted overflow).
__global__ __launch_bounds__(256) void knn_kernel(
    const float* __restrict__ p1,
    const int* __restrict__ len1,
    float* __restrict__ out,
    int Nn, int P1, int P2, long long NPK) {

    int gw = (blockIdx.x * blockDim.x + threadIdx.x) >> 5;
    int lane = threadIdx.x & 31;
    if (gw >= Nn * P1) return;
    int n = gw / P1;
    int qs = gw - n * P1;
    int L1 = __ldg(&len1[n]);
    if (qs >= L1) {
        // Padded slots [L1,P1) biject onto padded rows i=qs: write zeros here.
        if (lane < KNN_K) {
            long long o = ((long long)n * P1 + qs) * KNN_K;
            out[o + lane] = 0.0f;
            out[NPK + o + lane] = 0.0f;
        }
        return;
    }

    int i = __ldg(&g_qidx[n * MAXP + qs]);
    const float* p = p1 + ((size_t)n * P1 + i) * 3;
    float x1 = __ldg(&p[0]), y1 = __ldg(&p[1]), z1 = __ldg(&p[2]);
    float s1 = sumsq_ref(x1, y1, z1);

    const float4* pk = g_pack + (size_t)n * MAXP;
    const float* ps2 = g_s2 + (size_t)n * MAXP;
    const int* bs = g_bstart + n * (NBB + 1);

    int bz = binz(z1);

    float ld = FINF; int lj = 0x7fffffff;
    float b15d = FINF; int b15j = 0x7fffffff;
    bool inited = false;
    const float eps = 1e-4f;

    auto scan = [&](int from, int to) {
        int base = from;
        if (!inited && from < to) {
            int t = from + lane;
            float d; int jj;
            if (t < to) {
                float4 q = __ldg(&pk[t]);
                float s2 = __ldg(&ps2[t]);
                float dot = __fmaf_rn(z1, q.z,
                            __fmaf_rn(y1, q.y,
                            __fmul_rn(x1, q.x)));
                d = __fmaf_rn(-2.0f, dot, __fadd_rn(s1, s2));
                jj = __float_as_int(q.w);
            } else { d = FINF; jj = 0x7fffffff; }
            BSORT32(d, jj)
            ld = d; lj = jj;
            b15d = __shfl_sync(FULLM, ld, 15);
            b15j = __shfl_sync(FULLM, lj, 15);
            inited = true;
            base = from + 32;
        }
        for (; base < to; base += 32) {
            int t = base + lane;
            float d; int jj;
            if (t < to) {
                float4 q = __ldg(&pk[t]);
                float s2 = __ldg(&ps2[t]);
                float dot = __fmaf_rn(z1, q.z,
                            __fmaf_rn(y1, q.y,
                            __fmul_rn(x1, q.x)));
                d = __fmaf_rn(-2.0f, dot, __fadd_rn(s1, s2));
                jj = __float_as_int(q.w);
            } else { d = FINF; jj = 0x7fffffff; }
            bool acc = LEX_LT(d, jj, b15d, b15j);
            unsigned am = __ballot_sync(FULLM, acc);
            if (!am) continue;
            if (__popc(am) >= 8) {
                // Bulk path: sort batch, bitonic-merge with list (keep lowest 32).
                BSORT32(d, jj)
                float rd = __shfl_sync(FULLM, d, 31 - lane);
                int   rj = __shfl_sync(FULLM, jj, 31 - lane);
                bool keep = LEX_LT(ld, lj, rd, rj);
                float md = keep ? ld : rd;
                int   mj = keep ? lj : rj;
#pragma unroll
                for (int j = 16; j > 0; j >>= 1) {
                    float od = __shfl_xor_sync(FULLM, md, j);
                    int   oj = __shfl_xor_sync(FULLM, mj, j);
                    bool lower = ((lane & j) == 0);
                    bool mine_lt = LEX_LT(md, mj, od, oj);
                    bool take = (mine_lt != lower);
                    md = take ? od : md;
                    mj = take ? oj : mj;
                }
                ld = md; lj = mj;
            } else {
                while (am) {
                    int src = __ffs(am) - 1;
                    am &= am - 1;
                    float cd = __shfl_sync(FULLM, d, src);
                    int   cj = __shfl_sync(FULLM, jj, src);
                    float pd = __shfl_up_sync(FULLM, ld, 1);
                    int   pj = __shfl_up_sync(FULLM, lj, 1);
                    if (LEX_LT(cd, cj, ld, lj)) {
                        bool here = (lane == 0) || LEX_LT(pd, pj, cd, cj);
                        ld = here ? cd : pd;
                        lj = here ? cj : pj;
                    }
                }
            }
            b15d = __shfl_sync(FULLM, ld, 15);
            b15j = __shfl_sync(FULLM, lj, 15);
        }
    };

    // y-window [yl, yr] for half-width h around y1 (float-clamped: h may be inf).
    auto ybounds = [&](float h, int& yl, int& yr) {
        float fl = (y1 - h - BMIN) * INVY;
        float fr = (y1 + h - BMIN) * INVY;
        yl = (int)fminf(fmaxf(fl, 0.0f), (float)(NBY - 1));
        yr = (int)fminf(fmaxf(fr, 0.0f), (float)(NBY - 1));
    };

    // Bootstrap: fixed-width y-window (no expansion loop, 2 boundary loads).
    // Establishes tau; if it yields <16 candidates (sparse tails), tau stays
    // +inf and the tau-driven remainder below widens automatically -> exact.
    int rowb = bz * NBY;
    int ylo0, yhi0;
    ybounds(H0, ylo0, yhi0);
    scan(__ldg(&bs[rowb + ylo0]), __ldg(&bs[rowb + yhi0 + 1]));

    // Own-row remainder (disjoint from bootstrap; stale tau => superset, exact).
    {
        float tau = b15d;
        float h = sqrtf(fmaxf(tau + eps, 0.0f));
        int yl, yr; ybounds(h, yl, yr);
        if (yl < ylo0) scan(__ldg(&bs[rowb + yl]), __ldg(&bs[rowb + ylo0]));
        if (yr > yhi0) scan(__ldg(&bs[rowb + yhi0 + 1]), __ldg(&bs[rowb + yr + 1]));
    }

    // Rows outward with exact per-direction stop.
    int up = bz + 1, dn = bz - 1;
    bool uo = true, dno = true;
    while (uo || dno) {
        if (uo) {
            if (up >= NBZ) uo = false;
            else {
                float dz = fmaxf(BMIN + (float)up * WZ - z1, 0.0f);
                float tau = b15d;
                if (dz * dz > tau + eps) uo = false;
                else {
                    float h = sqrtf(fmaxf(tau + eps - dz * dz, 0.0f));
                    int yl, yr; ybounds(h, yl, yr);
                    int rb = up * NBY;
                    scan(__ldg(&bs[rb + yl]), __ldg(&bs[rb + yr + 1]));
                    up++;
                }
            }
        }
        if (dno) {
            if (dn < 0) dno = false;
            else {
                float dz = fmaxf(z1 - (BMIN + (float)(dn + 1) * WZ), 0.0f);
                float tau = b15d;
                if (dz * dz > tau + eps) dno = false;
                else {
                    float h = sqrtf(fmaxf(tau + eps - dz * dz, 0.0f));
                    int yl, yr; ybounds(h, yl, yr);
                    int rb = dn * NBY;
                    scan(__ldg(&bs[rb + yl]), __ldg(&bs[rb + yr + 1]));
                    dn--;
                }
            }
        }
    }

    if (lane < KNN_K) {
        long long o = ((long long)n * P1 + i) * KNN_K;
        out[o + lane] = (float)lj;
        out[NPK + o + lane] = ld;
    }
}

extern "C" void kernel_launch(void* const* d_in, const int* in_sizes, int n_in,
                              void* d_out, int out_size) {
    const float* pts[2] = {0, 0};
    const int* lens[2] = {0, 0};
    int lsz[2] = {0, 0};
    int psz[2] = {0, 0};
    int npts = 0, nlen = 0;
    for (int i = 0; i < n_in; i++) {
        if (in_sizes[i] <= 1024) {
            if (nlen < 2) { lens[nlen] = (const int*)d_in[i]; lsz[nlen] = in_sizes[i]; nlen++; }
        } else {
            if (npts < 2) { pts[npts] = (const float*)d_in[i]; psz[npts] = in_sizes[i]; npts++; }
        }
    }
    const float* p1 = pts[0];
    const float* p2 = pts[1];
    const int* l1 = lens[0];
    const int* l2 = lens[1];

    int Nn = lsz[0];
    int P1 = psz[0] / (3 * Nn);
    int P2 = psz[1] / (3 * Nn);
    long long NPK = (long long)out_size / 2;   // first half idx, second half dists

    int P = (P1 > P2) ? P1 : P2;
    int ptblocks = (Nn * P + 255) / 256;

    zero_hist_kernel<<<(Nn * NBB + 255) / 256, 256>>>(Nn);
    hist_kernel<<<ptblocks, 256>>>(p1, p2, l1, l2, Nn, P1, P2);
    scan_kernel<<<Nn, 256>>>(Nn);
    scatter_kernel<<<ptblocks, 256>>>(p1, p2, l1, l2, Nn, P1, P2);

    long long threads = (long long)Nn * P1 * 32;
    int blocks = (int)((threads + 255) / 256);
    knn_kernel<<<blocks, 256>>>(p1, l1, (float*)d_out, Nn, P1, P2, NPK);
}